// round 1
// baseline (speedup 1.0000x reference)
#include <cuda_runtime.h>
#include <math.h>

// Problem dims (fixed by the reference)
#define T   4096      // B*S tokens
#define DD  1024      // hidden
#define EE  8         // experts
#define FF  2752      // ffn
#define CAP 512       // capacity = T/E

// -------------------- scratch (device globals; no allocs allowed) ----------
__device__ float g_gates[T * EE];        // softmax probs per token
__device__ float g_gateval[T];           // top-1 gate prob
__device__ float g_coef[T * 2];          // coefficient softmax
__device__ int   g_expert[T];            // argmax expert
__device__ int   g_kept[T];              // 1 if not dropped
__device__ int   g_toklist[EE * CAP];    // slot -> token
__device__ int   g_nkept[EE];            // kept tokens per expert
__device__ __align__(16) float g_H[(size_t)(EE * CAP + T) * FF];  // SwiGLU mid (MoE slots + residual)
__device__ __align__(16) float g_moe_y[(size_t)T * DD];
__device__ __align__(16) float g_mlp_y[(size_t)T * DD];

// -------------------- gating: logits, softmax, argmax, coef ---------------
__global__ void gating_kernel(const float* __restrict__ x,
                              const float* __restrict__ wg,
                              const float* __restrict__ cw,
                              const float* __restrict__ cb)
{
    const int t = blockIdx.x;
    const float* xr = x + (size_t)t * DD;
    float acc[10];
#pragma unroll
    for (int i = 0; i < 10; i++) acc[i] = 0.f;

    for (int d = threadIdx.x; d < DD; d += 128) {
        float xv = xr[d];
        const float* wgr = wg + (size_t)d * EE;
#pragma unroll
        for (int e = 0; e < EE; e++) acc[e] = fmaf(xv, wgr[e], acc[e]);
        acc[8] = fmaf(xv, cw[d * 2 + 0], acc[8]);
        acc[9] = fmaf(xv, cw[d * 2 + 1], acc[9]);
    }
#pragma unroll
    for (int i = 0; i < 10; i++)
#pragma unroll
        for (int o = 16; o > 0; o >>= 1)
            acc[i] += __shfl_down_sync(0xffffffffu, acc[i], o);

    __shared__ float red[4][10];
    int w = threadIdx.x >> 5, lane = threadIdx.x & 31;
    if (lane == 0) {
#pragma unroll
        for (int i = 0; i < 10; i++) red[w][i] = acc[i];
    }
    __syncthreads();
    if (threadIdx.x == 0) {
        float v[10];
#pragma unroll
        for (int i = 0; i < 10; i++)
            v[i] = red[0][i] + red[1][i] + red[2][i] + red[3][i];
        // softmax over experts
        float m = v[0];
#pragma unroll
        for (int e = 1; e < EE; e++) m = fmaxf(m, v[e]);
        float g[EE]; float s = 0.f;
#pragma unroll
        for (int e = 0; e < EE; e++) { g[e] = __expf(v[e] - m); s += g[e]; }
        float inv = 1.f / s;
        int best = 0; float bp = -1.f;
#pragma unroll
        for (int e = 0; e < EE; e++) {
            float p = g[e] * inv;
            g_gates[t * EE + e] = p;
            if (p > bp) { bp = p; best = e; }
        }
        g_expert[t]  = best;
        g_gateval[t] = bp;
        // coefficient softmax (2-way)
        float l0 = v[8] + cb[0], l1 = v[9] + cb[1];
        float mm = fmaxf(l0, l1);
        float e0 = __expf(l0 - mm), e1 = __expf(l1 - mm);
        float si = 1.f / (e0 + e1);
        g_coef[t * 2 + 0] = e0 * si;
        g_coef[t * 2 + 1] = e1 * si;
    }
}

// -------------------- scan: slots, capacity drop, l_aux, exp_counts -------
__global__ void scan_kernel(float* __restrict__ out, int out_size)
{
    __shared__ int   sh_e[T];      // 16KB
    __shared__ float sh_me[EE];
    __shared__ int   sh_cnt[EE];

    for (int t = threadIdx.x; t < T; t += blockDim.x) sh_e[t] = g_expert[t];

    // me[e] = sum_t gates[t,e]  (one warp per expert; 256 threads = 8 warps)
    int wid = threadIdx.x >> 5, lane = threadIdx.x & 31;
    {
        float s = 0.f;
        for (int t = lane; t < T; t += 32) s += g_gates[t * EE + wid];
#pragma unroll
        for (int o = 16; o > 0; o >>= 1) s += __shfl_down_sync(0xffffffffu, s, o);
        if (lane == 0) sh_me[wid] = s;
    }
    __syncthreads();

    if (threadIdx.x < EE) {
        int e = threadIdx.x;
        int cnt = 0;
        for (int t = 0; t < T; t++) {
            if (sh_e[t] == e) {
                if (cnt < CAP) { g_toklist[e * CAP + cnt] = t; g_kept[t] = 1; }
                else           { g_kept[t] = 0; }
                cnt++;
            }
        }
        sh_cnt[e]  = cnt;
        g_nkept[e] = cnt < CAP ? cnt : CAP;
    }
    __syncthreads();

    if (threadIdx.x == 0 && out_size >= T * DD + 1 + EE) {
        float la = 0.f;
        const float invT = 1.f / (float)T;
#pragma unroll
        for (int e = 0; e < EE; e++)
            la += (sh_me[e] * invT) * ((float)sh_cnt[e] * invT);
        out[(size_t)T * DD] = la * (float)EE;
#pragma unroll
        for (int e = 0; e < EE; e++)
            out[(size_t)T * DD + 1 + e] = (float)sh_cnt[e];
    }
}

// -------------------- fused SwiGLU up GEMM: H = silu(A@W1) * (A@W3) -------
// 64x64 tile, BK=16, 256 threads, 4x4 per thread, dual accumulators.
template <bool GATHER>
__global__ void __launch_bounds__(256)
up_kernel(const float* __restrict__ X,
          const float* __restrict__ W1g,
          const float* __restrict__ W3g)
{
    const int e     = GATHER ? blockIdx.z : 0;
    const int nrows = GATHER ? g_nkept[e] : T;
    const int m0    = blockIdx.y * 64;
    if (m0 >= nrows) return;
    const int n0 = blockIdx.x * 64;

    const float* W1 = W1g + (GATHER ? (size_t)e * DD * FF : 0);
    const float* W3 = W3g + (GATHER ? (size_t)e * DD * FF : 0);
    float* Hb = g_H + (GATHER ? (size_t)e * CAP * FF : (size_t)EE * CAP * FF);

    __shared__ float As[16][68];
    __shared__ float B1s[16][64];
    __shared__ float B3s[16][64];

    const int tid = threadIdx.x;
    const int ak = tid & 15, am = tid >> 4;   // A loader coords
    const int bn = tid & 63, bk = tid >> 6;   // B loader coords
    const int tx = tid & 15, ty = tid >> 4;   // compute coords

    const float* ap[4];
#pragma unroll
    for (int i = 0; i < 4; i++) {
        int gm = m0 + am + 16 * i;
        if (gm < nrows) {
            int row = GATHER ? g_toklist[e * CAP + gm] : gm;
            ap[i] = X + (size_t)row * DD;
        } else ap[i] = nullptr;
    }

    float acc1[4][4], acc3[4][4];
#pragma unroll
    for (int i = 0; i < 4; i++)
#pragma unroll
        for (int j = 0; j < 4; j++) { acc1[i][j] = 0.f; acc3[i][j] = 0.f; }

    for (int k0 = 0; k0 < DD; k0 += 16) {
#pragma unroll
        for (int i = 0; i < 4; i++)
            As[ak][am + 16 * i] = ap[i] ? ap[i][k0 + ak] : 0.f;
#pragma unroll
        for (int j = 0; j < 4; j++) {
            int kk = bk + 4 * j;
            B1s[kk][bn] = W1[(size_t)(k0 + kk) * FF + n0 + bn];
            B3s[kk][bn] = W3[(size_t)(k0 + kk) * FF + n0 + bn];
        }
        __syncthreads();
#pragma unroll
        for (int k = 0; k < 16; k++) {
            float a[4], b1[4], b3[4];
#pragma unroll
            for (int i = 0; i < 4; i++) a[i] = As[k][ty * 4 + i];
#pragma unroll
            for (int j = 0; j < 4; j++) { b1[j] = B1s[k][tx * 4 + j]; b3[j] = B3s[k][tx * 4 + j]; }
#pragma unroll
            for (int i = 0; i < 4; i++)
#pragma unroll
                for (int j = 0; j < 4; j++) {
                    acc1[i][j] = fmaf(a[i], b1[j], acc1[i][j]);
                    acc3[i][j] = fmaf(a[i], b3[j], acc3[i][j]);
                }
        }
        __syncthreads();
    }

#pragma unroll
    for (int i = 0; i < 4; i++) {
        int m = m0 + ty * 4 + i;
        if (m >= nrows) continue;
        float* Hr = Hb + (size_t)m * FF + n0 + tx * 4;
#pragma unroll
        for (int j = 0; j < 4; j++) {
            float h1 = acc1[i][j], h3 = acc3[i][j];
            Hr[j] = (h1 / (1.f + __expf(-h1))) * h3;   // silu(h1)*h3
        }
    }
}

// -------------------- down GEMM: Y = H @ W2, scattered to token rows ------
template <bool GATHER>
__global__ void __launch_bounds__(256)
down_kernel(const float* __restrict__ W2g)
{
    const int e     = GATHER ? blockIdx.z : 0;
    const int nrows = GATHER ? g_nkept[e] : T;
    const int m0    = blockIdx.y * 64;
    if (m0 >= nrows) return;
    const int n0 = blockIdx.x * 64;

    const float* W2 = W2g + (GATHER ? (size_t)e * FF * DD : 0);
    const float* Hb = g_H + (GATHER ? (size_t)e * CAP * FF : (size_t)EE * CAP * FF);

    __shared__ float As[16][68];
    __shared__ float Bs[16][64];

    const int tid = threadIdx.x;
    const int ak = tid & 15, am = tid >> 4;
    const int bn = tid & 63, bk = tid >> 6;
    const int tx = tid & 15, ty = tid >> 4;

    const float* ap[4];
#pragma unroll
    for (int i = 0; i < 4; i++) {
        int gm = m0 + am + 16 * i;
        ap[i] = (gm < nrows) ? (Hb + (size_t)gm * FF) : nullptr;
    }

    float acc[4][4];
#pragma unroll
    for (int i = 0; i < 4; i++)
#pragma unroll
        for (int j = 0; j < 4; j++) acc[i][j] = 0.f;

    for (int k0 = 0; k0 < FF; k0 += 16) {
#pragma unroll
        for (int i = 0; i < 4; i++)
            As[ak][am + 16 * i] = ap[i] ? ap[i][k0 + ak] : 0.f;
#pragma unroll
        for (int j = 0; j < 4; j++) {
            int kk = bk + 4 * j;
            Bs[kk][bn] = W2[(size_t)(k0 + kk) * DD + n0 + bn];
        }
        __syncthreads();
#pragma unroll
        for (int k = 0; k < 16; k++) {
            float a[4], b[4];
#pragma unroll
            for (int i = 0; i < 4; i++) a[i] = As[k][ty * 4 + i];
#pragma unroll
            for (int j = 0; j < 4; j++) b[j] = Bs[k][tx * 4 + j];
#pragma unroll
            for (int i = 0; i < 4; i++)
#pragma unroll
                for (int j = 0; j < 4; j++)
                    acc[i][j] = fmaf(a[i], b[j], acc[i][j]);
        }
        __syncthreads();
    }

#pragma unroll
    for (int i = 0; i < 4; i++) {
        int m = m0 + ty * 4 + i;
        if (m >= nrows) continue;
        int row = GATHER ? g_toklist[e * CAP + m] : m;
        float* Y = (GATHER ? g_moe_y : g_mlp_y) + (size_t)row * DD + n0 + tx * 4;
#pragma unroll
        for (int j = 0; j < 4; j++) Y[j] = acc[i][j];
    }
}

// -------------------- combine: out = coef0*gate*moe + coef1*mlp -----------
__global__ void combine_kernel(float* __restrict__ out)
{
    int i4 = blockIdx.x * blockDim.x + threadIdx.x;   // float4 index
    if (i4 >= T * DD / 4) return;
    int t = i4 >> 8;                                   // (i4*4)/1024
    float c1 = g_coef[2 * t + 1];
    float gm = g_kept[t] ? g_coef[2 * t] * g_gateval[t] : 0.f;

    float4 mo = reinterpret_cast<const float4*>(g_moe_y)[i4];
    float4 pl = reinterpret_cast<const float4*>(g_mlp_y)[i4];
    float4 r;
    r.x = gm * mo.x + c1 * pl.x;
    r.y = gm * mo.y + c1 * pl.y;
    r.z = gm * mo.z + c1 * pl.z;
    r.w = gm * mo.w + c1 * pl.w;
    reinterpret_cast<float4*>(out)[i4] = r;
}

// -------------------- launch ----------------------------------------------
extern "C" void kernel_launch(void* const* d_in, const int* in_sizes, int n_in,
                              void* d_out, int out_size)
{
    const float* x   = (const float*)d_in[0];
    const float* wg  = (const float*)d_in[1];
    const float* w1  = (const float*)d_in[2];
    const float* w3  = (const float*)d_in[3];
    const float* w2  = (const float*)d_in[4];
    const float* rw1 = (const float*)d_in[5];
    const float* rw3 = (const float*)d_in[6];
    const float* rw2 = (const float*)d_in[7];
    const float* cw  = (const float*)d_in[8];
    const float* cb  = (const float*)d_in[9];
    float* out = (float*)d_out;

    gating_kernel<<<T, 128>>>(x, wg, cw, cb);
    scan_kernel<<<1, 256>>>(out, out_size);

    // MoE experts: fused SwiGLU up (gathered rows), then residual MLP up
    up_kernel<true ><<<dim3(FF / 64, CAP / 64, EE), 256>>>(x, w1, w3);
    up_kernel<false><<<dim3(FF / 64, T   / 64,  1), 256>>>(x, rw1, rw3);

    // Down projections
    down_kernel<true ><<<dim3(DD / 64, CAP / 64, EE), 256>>>(w2);
    down_kernel<false><<<dim3(DD / 64, T   / 64,  1), 256>>>(rw2);

    combine_kernel<<<(T * DD / 4 + 255) / 256, 256>>>(out);
}

// round 2
// speedup vs baseline: 2.3234x; 2.3234x over previous
#include <cuda_runtime.h>
#include <math.h>
#include <stdint.h>

// Problem dims (fixed by the reference)
#define T   4096      // B*S tokens
#define DD  1024      // hidden
#define EE  8         // experts
#define FF  2752      // ffn
#define CAP 512       // capacity = T/E

// -------------------- scratch (device globals; no allocs allowed) ----------
__device__ float g_gates[T * EE];
__device__ float g_gateval[T];
__device__ float g_coef[T * 2];
__device__ int   g_expert[T];
__device__ int   g_kept[T];
__device__ int   g_toklist[EE * CAP];
__device__ int   g_nkept[EE];
__device__ __align__(16) float g_H[(size_t)(EE * CAP + T) * FF];
__device__ __align__(16) float g_moe_y[(size_t)T * DD];
__device__ __align__(16) float g_mlp_y[(size_t)T * DD];

// -------------------- helpers ---------------------------------------------
__device__ __forceinline__ uint32_t f2tf(float x) {
    uint32_t r;
    asm("cvt.rna.tf32.f32 %0, %1;" : "=r"(r) : "f"(x));
    return r;
}

__device__ __forceinline__ void mma8(float* d, const uint32_t* a, const uint32_t* b) {
    asm volatile(
        "mma.sync.aligned.m16n8k8.row.col.f32.tf32.tf32.f32 "
        "{%0,%1,%2,%3}, {%4,%5,%6,%7}, {%8,%9}, {%0,%1,%2,%3};"
        : "+f"(d[0]), "+f"(d[1]), "+f"(d[2]), "+f"(d[3])
        : "r"(a[0]), "r"(a[1]), "r"(a[2]), "r"(a[3]),
          "r"(b[0]), "r"(b[1]));
}

__device__ __forceinline__ float silu_f(float x) {
    return x / (1.f + __expf(-x));
}

// -------------------- gating: logits, softmax, argmax, coef ---------------
__global__ void gating_kernel(const float* __restrict__ x,
                              const float* __restrict__ wg,
                              const float* __restrict__ cw,
                              const float* __restrict__ cb)
{
    const int t = blockIdx.x;
    const float* xr = x + (size_t)t * DD;
    float acc[10];
#pragma unroll
    for (int i = 0; i < 10; i++) acc[i] = 0.f;

    for (int d = threadIdx.x; d < DD; d += 128) {
        float xv = xr[d];
        const float* wgr = wg + (size_t)d * EE;
#pragma unroll
        for (int e = 0; e < EE; e++) acc[e] = fmaf(xv, wgr[e], acc[e]);
        acc[8] = fmaf(xv, cw[d * 2 + 0], acc[8]);
        acc[9] = fmaf(xv, cw[d * 2 + 1], acc[9]);
    }
#pragma unroll
    for (int i = 0; i < 10; i++)
#pragma unroll
        for (int o = 16; o > 0; o >>= 1)
            acc[i] += __shfl_down_sync(0xffffffffu, acc[i], o);

    __shared__ float red[4][10];
    int w = threadIdx.x >> 5, lane = threadIdx.x & 31;
    if (lane == 0) {
#pragma unroll
        for (int i = 0; i < 10; i++) red[w][i] = acc[i];
    }
    __syncthreads();
    if (threadIdx.x == 0) {
        float v[10];
#pragma unroll
        for (int i = 0; i < 10; i++)
            v[i] = red[0][i] + red[1][i] + red[2][i] + red[3][i];
        float m = v[0];
#pragma unroll
        for (int e = 1; e < EE; e++) m = fmaxf(m, v[e]);
        float g[EE]; float s = 0.f;
#pragma unroll
        for (int e = 0; e < EE; e++) { g[e] = __expf(v[e] - m); s += g[e]; }
        float inv = 1.f / s;
        int best = 0; float bp = -1.f;
#pragma unroll
        for (int e = 0; e < EE; e++) {
            float p = g[e] * inv;
            g_gates[t * EE + e] = p;
            if (p > bp) { bp = p; best = e; }
        }
        g_expert[t]  = best;
        g_gateval[t] = bp;
        float l0 = v[8] + cb[0], l1 = v[9] + cb[1];
        float mm = fmaxf(l0, l1);
        float e0 = __expf(l0 - mm), e1 = __expf(l1 - mm);
        float si = 1.f / (e0 + e1);
        g_coef[t * 2 + 0] = e0 * si;
        g_coef[t * 2 + 1] = e1 * si;
    }
}

// -------------------- scan: slots, capacity drop, l_aux, exp_counts -------
__global__ void scan_kernel(float* __restrict__ out, int out_size)
{
    __shared__ int   sh_e[T];
    __shared__ float sh_me[EE];
    __shared__ int   sh_cnt[EE];

    for (int t = threadIdx.x; t < T; t += blockDim.x) sh_e[t] = g_expert[t];

    int wid = threadIdx.x >> 5, lane = threadIdx.x & 31;
    {
        float s = 0.f;
        for (int t = lane; t < T; t += 32) s += g_gates[t * EE + wid];
#pragma unroll
        for (int o = 16; o > 0; o >>= 1) s += __shfl_down_sync(0xffffffffu, s, o);
        if (lane == 0) sh_me[wid] = s;
    }
    __syncthreads();

    if (threadIdx.x < EE) {
        int e = threadIdx.x;
        int cnt = 0;
        for (int t = 0; t < T; t++) {
            if (sh_e[t] == e) {
                if (cnt < CAP) { g_toklist[e * CAP + cnt] = t; g_kept[t] = 1; }
                else           { g_kept[t] = 0; }
                cnt++;
            }
        }
        sh_cnt[e]  = cnt;
        g_nkept[e] = cnt < CAP ? cnt : CAP;
    }
    __syncthreads();

    if (threadIdx.x == 0 && out_size >= T * DD + 1 + EE) {
        float la = 0.f;
        const float invT = 1.f / (float)T;
#pragma unroll
        for (int e = 0; e < EE; e++)
            la += (sh_me[e] * invT) * ((float)sh_cnt[e] * invT);
        out[(size_t)T * DD] = la * (float)EE;
#pragma unroll
        for (int e = 0; e < EE; e++)
            out[(size_t)T * DD + 1 + e] = (float)sh_cnt[e];
    }
}

// -------------------- tf32 tensor-core GEMM --------------------------------
// MODE 0: up gathered   A = X[toklist], B = w1,w3 (dual)  -> g_H expert region
// MODE 1: up residual   A = X,          B = rw1,rw3 (dual)-> g_H residual region
// MODE 2: down gathered A = g_H expert, B = w2            -> g_moe_y (scatter)
// MODE 3: down residual A = g_H resid,  B = rw2           -> g_mlp_y
// Block tile 128x64x16, 256 threads, 8 warps (2M x 4N), warp tile 64x16.
// mma.m16n8k8.tf32 with RNA conversion at smem fill.

#define BM 128
#define BN 64
#define BK 16

template <int MODE>
__global__ void __launch_bounds__(256)
gemm_kernel(const float* __restrict__ Xin,
            const float* __restrict__ B1g,
            const float* __restrict__ B3g)
{
    constexpr bool GATHER = (MODE == 0 || MODE == 2);
    constexpr bool DUAL   = (MODE <= 1);
    constexpr int  KD     = DUAL ? DD : FF;
    constexpr int  ND     = DUAL ? FF : DD;
    constexpr int  NB     = DUAL ? 2 : 1;

    const int e     = GATHER ? blockIdx.z : 0;
    const int nrows = GATHER ? g_nkept[e] : T;
    const int m0    = blockIdx.y * BM;
    if (m0 >= nrows) return;
    const int n0 = blockIdx.x * BN;

    const float* B1 = B1g + (MODE == 0 ? (size_t)e * DD * FF
                          : (MODE == 2 ? (size_t)e * FF * DD : 0));
    const float* B3 = DUAL ? (B3g + (MODE == 0 ? (size_t)e * DD * FF : 0)) : nullptr;

    __shared__ uint32_t As[2][BM][BK + 4];
    __shared__ uint32_t Bs[2][NB][BK][BN + 8];

    const int tid  = threadIdx.x;
    const int lane = tid & 31;
    const int warp = tid >> 5;
    const int wm   = (warp & 1) * 64;       // warp M origin in tile
    const int wn   = (warp >> 1) * 16;      // warp N origin in tile
    const int lg   = lane >> 2;             // groupID
    const int lq   = lane & 3;              // threadID_in_group

    // A loader: each thread owns 2 rows (tid>>2, tid>>2+64), 4 consecutive k
    const float* aptr[2];
    const int arow = tid >> 2;
    const int akq  = (tid & 3) * 4;
#pragma unroll
    for (int i = 0; i < 2; i++) {
        int gr = m0 + arow + i * 64;
        if (gr < nrows) {
            if      (MODE == 0) aptr[i] = Xin + (size_t)g_toklist[e * CAP + gr] * DD;
            else if (MODE == 1) aptr[i] = Xin + (size_t)gr * DD;
            else if (MODE == 2) aptr[i] = g_H + ((size_t)e * CAP + gr) * FF;
            else                aptr[i] = g_H + ((size_t)(EE * CAP) + gr) * FF;
        } else aptr[i] = nullptr;
    }
    // B loader: row tid>>4 (0..15), 4 consecutive n
    const int bkr = tid >> 4;
    const int bnq = (tid & 15) * 4;

    float acc1[4][2][4];
    float acc3[DUAL ? 4 : 1][2][4];
#pragma unroll
    for (int mi = 0; mi < 4; mi++)
#pragma unroll
        for (int ni = 0; ni < 2; ni++)
#pragma unroll
            for (int j = 0; j < 4; j++) {
                acc1[mi][ni][j] = 0.f;
                if (DUAL) acc3[mi][ni][j] = 0.f;
            }

    float4 av[2], bv1, bv3;
    auto ldg_tile = [&](int k0) {
#pragma unroll
        for (int i = 0; i < 2; i++)
            av[i] = aptr[i] ? *(const float4*)(aptr[i] + k0 + akq)
                            : make_float4(0.f, 0.f, 0.f, 0.f);
        bv1 = *(const float4*)(B1 + (size_t)(k0 + bkr) * ND + n0 + bnq);
        if (DUAL) bv3 = *(const float4*)(B3 + (size_t)(k0 + bkr) * ND + n0 + bnq);
    };
    auto sts_tile = [&](int s) {
#pragma unroll
        for (int i = 0; i < 2; i++) {
            uint4 u;
            u.x = f2tf(av[i].x); u.y = f2tf(av[i].y);
            u.z = f2tf(av[i].z); u.w = f2tf(av[i].w);
            *(uint4*)&As[s][arow + i * 64][akq] = u;
        }
        {
            uint4 u;
            u.x = f2tf(bv1.x); u.y = f2tf(bv1.y);
            u.z = f2tf(bv1.z); u.w = f2tf(bv1.w);
            *(uint4*)&Bs[s][0][bkr][bnq] = u;
        }
        if (DUAL) {
            uint4 u;
            u.x = f2tf(bv3.x); u.y = f2tf(bv3.y);
            u.z = f2tf(bv3.z); u.w = f2tf(bv3.w);
            *(uint4*)&Bs[s][NB - 1][bkr][bnq] = u;
        }
    };

    ldg_tile(0);
    sts_tile(0);
    __syncthreads();

    const int nk = KD / BK;
    for (int kt = 0; kt < nk; kt++) {
        const int cur = kt & 1, nxt = cur ^ 1;
        if (kt + 1 < nk) ldg_tile((kt + 1) * BK);

#pragma unroll
        for (int ks = 0; ks < 2; ks++) {
            const int k8 = ks * 8;
            uint32_t af[4][4];
#pragma unroll
            for (int mi = 0; mi < 4; mi++) {
                int r = wm + mi * 16 + lg;
                af[mi][0] = As[cur][r][k8 + lq];
                af[mi][1] = As[cur][r + 8][k8 + lq];
                af[mi][2] = As[cur][r][k8 + lq + 4];
                af[mi][3] = As[cur][r + 8][k8 + lq + 4];
            }
            uint32_t bf1[2][2], bf3[2][2];
#pragma unroll
            for (int ni = 0; ni < 2; ni++) {
                int c = wn + ni * 8 + lg;
                bf1[ni][0] = Bs[cur][0][k8 + lq][c];
                bf1[ni][1] = Bs[cur][0][k8 + lq + 4][c];
                if (DUAL) {
                    bf3[ni][0] = Bs[cur][NB - 1][k8 + lq][c];
                    bf3[ni][1] = Bs[cur][NB - 1][k8 + lq + 4][c];
                }
            }
#pragma unroll
            for (int mi = 0; mi < 4; mi++)
#pragma unroll
                for (int ni = 0; ni < 2; ni++) {
                    mma8(acc1[mi][ni], af[mi], bf1[ni]);
                    if (DUAL) mma8(acc3[mi][ni], af[mi], bf3[ni]);
                }
        }

        if (kt + 1 < nk) sts_tile(nxt);
        __syncthreads();
    }

    // -------- epilogue --------
#pragma unroll
    for (int mi = 0; mi < 4; mi++) {
#pragma unroll
        for (int half = 0; half < 2; half++) {
            int row = m0 + wm + mi * 16 + lg + half * 8;
            if (row >= nrows) continue;
            float* obase;
            if      (MODE == 0) obase = g_H + ((size_t)e * CAP + row) * FF;
            else if (MODE == 1) obase = g_H + ((size_t)(EE * CAP) + row) * FF;
            else if (MODE == 2) obase = g_moe_y + (size_t)g_toklist[e * CAP + row] * DD;
            else                obase = g_mlp_y + (size_t)row * DD;
#pragma unroll
            for (int ni = 0; ni < 2; ni++) {
                int c = n0 + wn + ni * 8 + 2 * lq;
                float2 v;
                if (DUAL) {
                    float h1a = acc1[mi][ni][2 * half + 0];
                    float h1b = acc1[mi][ni][2 * half + 1];
                    float h3a = acc3[mi][ni][2 * half + 0];
                    float h3b = acc3[mi][ni][2 * half + 1];
                    v.x = silu_f(h1a) * h3a;
                    v.y = silu_f(h1b) * h3b;
                } else {
                    v.x = acc1[mi][ni][2 * half + 0];
                    v.y = acc1[mi][ni][2 * half + 1];
                }
                *(float2*)(obase + c) = v;
            }
        }
    }
}

// -------------------- combine: out = coef0*gate*moe + coef1*mlp -----------
__global__ void combine_kernel(float* __restrict__ out)
{
    int i4 = blockIdx.x * blockDim.x + threadIdx.x;
    if (i4 >= T * DD / 4) return;
    int t = i4 >> 8;
    float c1 = g_coef[2 * t + 1];
    float gm = g_kept[t] ? g_coef[2 * t] * g_gateval[t] : 0.f;

    float4 mo = reinterpret_cast<const float4*>(g_moe_y)[i4];
    float4 pl = reinterpret_cast<const float4*>(g_mlp_y)[i4];
    float4 r;
    r.x = gm * mo.x + c1 * pl.x;
    r.y = gm * mo.y + c1 * pl.y;
    r.z = gm * mo.z + c1 * pl.z;
    r.w = gm * mo.w + c1 * pl.w;
    reinterpret_cast<float4*>(out)[i4] = r;
}

// -------------------- launch ----------------------------------------------
extern "C" void kernel_launch(void* const* d_in, const int* in_sizes, int n_in,
                              void* d_out, int out_size)
{
    const float* x   = (const float*)d_in[0];
    const float* wg  = (const float*)d_in[1];
    const float* w1  = (const float*)d_in[2];
    const float* w3  = (const float*)d_in[3];
    const float* w2  = (const float*)d_in[4];
    const float* rw1 = (const float*)d_in[5];
    const float* rw3 = (const float*)d_in[6];
    const float* rw2 = (const float*)d_in[7];
    const float* cw  = (const float*)d_in[8];
    const float* cb  = (const float*)d_in[9];
    float* out = (float*)d_out;

    gating_kernel<<<T, 128>>>(x, wg, cw, cb);
    scan_kernel<<<1, 256>>>(out, out_size);

    // up projections (fused SwiGLU, dual-B tensor GEMM)
    gemm_kernel<0><<<dim3(FF / BN, CAP / BM, EE), 256>>>(x, w1, w3);
    gemm_kernel<1><<<dim3(FF / BN, T   / BM, 1 ), 256>>>(x, rw1, rw3);

    // down projections
    gemm_kernel<2><<<dim3(DD / BN, CAP / BM, EE), 256>>>(nullptr, w2, nullptr);
    gemm_kernel<3><<<dim3(DD / BN, T   / BM, 1 ), 256>>>(nullptr, rw2, nullptr);

    combine_kernel<<<(T * DD / 4 + 255) / 256, 256>>>(out);
}

// round 3
// speedup vs baseline: 2.4100x; 1.0373x over previous
#include <cuda_runtime.h>
#include <math.h>
#include <stdint.h>

// Problem dims (fixed by the reference)
#define T   4096      // B*S tokens
#define DD  1024      // hidden
#define EE  8         // experts
#define FF  2752      // ffn
#define CAP 512       // capacity = T/E

// -------------------- scratch (device globals; no allocs allowed) ----------
__device__ float g_gates[T * EE];
__device__ float g_gateval[T];
__device__ float g_coef[T * 2];
__device__ int   g_expert[T];
__device__ int   g_kept[T];
__device__ int   g_toklist[EE * CAP];
__device__ int   g_nkept[EE];
__device__ __align__(16) float g_H[(size_t)(EE * CAP + T) * FF];
__device__ __align__(16) float g_moe_y[(size_t)T * DD];
__device__ __align__(16) float g_mlp_y[(size_t)T * DD];

// -------------------- helpers ---------------------------------------------
__device__ __forceinline__ uint32_t f2tf(float x) {
    uint32_t r;
    asm("cvt.rna.tf32.f32 %0, %1;" : "=r"(r) : "f"(x));
    return r;
}

__device__ __forceinline__ void mma8(float* d, const uint32_t* a, const uint32_t* b) {
    asm volatile(
        "mma.sync.aligned.m16n8k8.row.col.f32.tf32.tf32.f32 "
        "{%0,%1,%2,%3}, {%4,%5,%6,%7}, {%8,%9}, {%0,%1,%2,%3};"
        : "+f"(d[0]), "+f"(d[1]), "+f"(d[2]), "+f"(d[3])
        : "r"(a[0]), "r"(a[1]), "r"(a[2]), "r"(a[3]),
          "r"(b[0]), "r"(b[1]));
}

// ldmatrix.x4: loads a 16x8 tf32 atom straight into the m16n8k8 A fragment.
__device__ __forceinline__ void ldsm4(uint32_t* r, uint32_t saddr) {
    asm volatile(
        "ldmatrix.sync.aligned.m8n8.x4.shared.b16 {%0,%1,%2,%3}, [%4];"
        : "=r"(r[0]), "=r"(r[1]), "=r"(r[2]), "=r"(r[3])
        : "r"(saddr));
}

__device__ __forceinline__ float silu_f(float x) {
    return x / (1.f + __expf(-x));
}

// -------------------- gating: logits, softmax, argmax, coef ---------------
__global__ void gating_kernel(const float* __restrict__ x,
                              const float* __restrict__ wg,
                              const float* __restrict__ cw,
                              const float* __restrict__ cb)
{
    const int t = blockIdx.x;
    const float* xr = x + (size_t)t * DD;
    float acc[10];
#pragma unroll
    for (int i = 0; i < 10; i++) acc[i] = 0.f;

    for (int d = threadIdx.x; d < DD; d += 128) {
        float xv = xr[d];
        const float* wgr = wg + (size_t)d * EE;
#pragma unroll
        for (int e = 0; e < EE; e++) acc[e] = fmaf(xv, wgr[e], acc[e]);
        acc[8] = fmaf(xv, cw[d * 2 + 0], acc[8]);
        acc[9] = fmaf(xv, cw[d * 2 + 1], acc[9]);
    }
#pragma unroll
    for (int i = 0; i < 10; i++)
#pragma unroll
        for (int o = 16; o > 0; o >>= 1)
            acc[i] += __shfl_down_sync(0xffffffffu, acc[i], o);

    __shared__ float red[4][10];
    int w = threadIdx.x >> 5, lane = threadIdx.x & 31;
    if (lane == 0) {
#pragma unroll
        for (int i = 0; i < 10; i++) red[w][i] = acc[i];
    }
    __syncthreads();
    if (threadIdx.x == 0) {
        float v[10];
#pragma unroll
        for (int i = 0; i < 10; i++)
            v[i] = red[0][i] + red[1][i] + red[2][i] + red[3][i];
        float m = v[0];
#pragma unroll
        for (int e = 1; e < EE; e++) m = fmaxf(m, v[e]);
        float g[EE]; float s = 0.f;
#pragma unroll
        for (int e = 0; e < EE; e++) { g[e] = __expf(v[e] - m); s += g[e]; }
        float inv = 1.f / s;
        int best = 0; float bp = -1.f;
#pragma unroll
        for (int e = 0; e < EE; e++) {
            float p = g[e] * inv;
            g_gates[t * EE + e] = p;
            if (p > bp) { bp = p; best = e; }
        }
        g_expert[t]  = best;
        g_gateval[t] = bp;
        float l0 = v[8] + cb[0], l1 = v[9] + cb[1];
        float mm = fmaxf(l0, l1);
        float e0 = __expf(l0 - mm), e1 = __expf(l1 - mm);
        float si = 1.f / (e0 + e1);
        g_coef[t * 2 + 0] = e0 * si;
        g_coef[t * 2 + 1] = e1 * si;
    }
}

// -------------------- scan: slots, capacity drop, l_aux, exp_counts -------
__global__ void scan_kernel(float* __restrict__ out, int out_size)
{
    __shared__ int   sh_e[T];
    __shared__ float sh_me[EE];
    __shared__ int   sh_cnt[EE];

    for (int t = threadIdx.x; t < T; t += blockDim.x) sh_e[t] = g_expert[t];

    int wid = threadIdx.x >> 5, lane = threadIdx.x & 31;
    {
        float s = 0.f;
        for (int t = lane; t < T; t += 32) s += g_gates[t * EE + wid];
#pragma unroll
        for (int o = 16; o > 0; o >>= 1) s += __shfl_down_sync(0xffffffffu, s, o);
        if (lane == 0) sh_me[wid] = s;
    }
    __syncthreads();

    if (threadIdx.x < EE) {
        int e = threadIdx.x;
        int cnt = 0;
        for (int t = 0; t < T; t++) {
            if (sh_e[t] == e) {
                if (cnt < CAP) { g_toklist[e * CAP + cnt] = t; g_kept[t] = 1; }
                else           { g_kept[t] = 0; }
                cnt++;
            }
        }
        sh_cnt[e]  = cnt;
        g_nkept[e] = cnt < CAP ? cnt : CAP;
    }
    __syncthreads();

    if (threadIdx.x == 0 && out_size >= T * DD + 1 + EE) {
        float la = 0.f;
        const float invT = 1.f / (float)T;
#pragma unroll
        for (int e = 0; e < EE; e++)
            la += (sh_me[e] * invT) * ((float)sh_cnt[e] * invT);
        out[(size_t)T * DD] = la * (float)EE;
#pragma unroll
        for (int e = 0; e < EE; e++)
            out[(size_t)T * DD + 1 + e] = (float)sh_cnt[e];
    }
}

// -------------------- tf32 tensor-core GEMM --------------------------------
// MODE 0: up gathered   A = X[toklist], B = w1,w3 (dual)  -> g_H expert region
// MODE 1: up residual   A = X,          B = rw1,rw3 (dual)-> g_H residual region
// MODE 2: down gathered A = g_H expert, B = w2            -> g_moe_y (scatter)
// MODE 3: down residual A = g_H resid,  B = rw2           -> g_mlp_y
// Block tile 128x64x16, 256 threads, 8 warps (2M x 4N), warp tile 64x16.
// A fragments via ldmatrix.x4 (one LDSM per 16x8 atom).

#define BM 128
#define BN 64
#define BK 16

template <int MODE>
__global__ void __launch_bounds__(256)
gemm_kernel(const float* __restrict__ Xin,
            const float* __restrict__ B1g,
            const float* __restrict__ B3g)
{
    constexpr bool GATHER = (MODE == 0 || MODE == 2);
    constexpr bool DUAL   = (MODE <= 1);
    constexpr int  KD     = DUAL ? DD : FF;
    constexpr int  ND     = DUAL ? FF : DD;
    constexpr int  NB     = DUAL ? 2 : 1;

    const int e     = GATHER ? blockIdx.z : 0;
    const int nrows = GATHER ? g_nkept[e] : T;
    const int m0    = blockIdx.y * BM;
    if (m0 >= nrows) return;
    const int n0 = blockIdx.x * BN;

    const float* B1 = B1g + (MODE == 0 ? (size_t)e * DD * FF
                          : (MODE == 2 ? (size_t)e * FF * DD : 0));
    const float* B3 = DUAL ? (B3g + (MODE == 0 ? (size_t)e * DD * FF : 0)) : nullptr;

    __shared__ uint32_t As[2][BM][BK + 4];
    __shared__ uint32_t Bs[2][NB][BK][BN + 8];

    const int tid  = threadIdx.x;
    const int lane = tid & 31;
    const int warp = tid >> 5;
    const int wm   = (warp & 1) * 64;       // warp M origin in tile
    const int wn   = (warp >> 1) * 16;      // warp N origin in tile
    const int lq   = lane & 3;              // threadID_in_group

    // ldmatrix lane address components (row/col inside a 16x8 atom)
    const int lrr = (lane & 7) + (lane & 8);        // 0..15
    const int lcc = (lane & 16) >> 2;               // 0 or 4
    const uint32_t As_u32 = (uint32_t)__cvta_generic_to_shared(&As[0][0][0]);
    const uint32_t lane_a = As_u32 + ((uint32_t)((wm + lrr) * (BK + 4) + lcc)) * 4u;
    constexpr uint32_t ABUF = BM * (BK + 4) * 4;    // bytes per A buffer

    // A loader: each thread owns 2 rows (tid>>2, tid>>2+64), 4 consecutive k
    const float* aptr[2];
    const int arow = tid >> 2;
    const int akq  = (tid & 3) * 4;
#pragma unroll
    for (int i = 0; i < 2; i++) {
        int gr = m0 + arow + i * 64;
        if (gr < nrows) {
            if      (MODE == 0) aptr[i] = Xin + (size_t)g_toklist[e * CAP + gr] * DD;
            else if (MODE == 1) aptr[i] = Xin + (size_t)gr * DD;
            else if (MODE == 2) aptr[i] = g_H + ((size_t)e * CAP + gr) * FF;
            else                aptr[i] = g_H + ((size_t)(EE * CAP) + gr) * FF;
        } else aptr[i] = nullptr;
    }
    // B loader: row tid>>4 (0..15), 4 consecutive n
    const int bkr = tid >> 4;
    const int bnq = (tid & 15) * 4;

    float acc1[4][2][4];
    float acc3[DUAL ? 4 : 1][2][4];
#pragma unroll
    for (int mi = 0; mi < 4; mi++)
#pragma unroll
        for (int ni = 0; ni < 2; ni++)
#pragma unroll
            for (int j = 0; j < 4; j++) {
                acc1[mi][ni][j] = 0.f;
                if (DUAL) acc3[mi][ni][j] = 0.f;
            }

    float4 av[2], bv1, bv3;
    auto ldg_tile = [&](int k0) {
#pragma unroll
        for (int i = 0; i < 2; i++)
            av[i] = aptr[i] ? *(const float4*)(aptr[i] + k0 + akq)
                            : make_float4(0.f, 0.f, 0.f, 0.f);
        bv1 = *(const float4*)(B1 + (size_t)(k0 + bkr) * ND + n0 + bnq);
        if (DUAL) bv3 = *(const float4*)(B3 + (size_t)(k0 + bkr) * ND + n0 + bnq);
    };
    auto sts_tile = [&](int s) {
#pragma unroll
        for (int i = 0; i < 2; i++) {
            uint4 u;
            u.x = f2tf(av[i].x); u.y = f2tf(av[i].y);
            u.z = f2tf(av[i].z); u.w = f2tf(av[i].w);
            *(uint4*)&As[s][arow + i * 64][akq] = u;
        }
        {
            uint4 u;
            u.x = f2tf(bv1.x); u.y = f2tf(bv1.y);
            u.z = f2tf(bv1.z); u.w = f2tf(bv1.w);
            *(uint4*)&Bs[s][0][bkr][bnq] = u;
        }
        if (DUAL) {
            uint4 u;
            u.x = f2tf(bv3.x); u.y = f2tf(bv3.y);
            u.z = f2tf(bv3.z); u.w = f2tf(bv3.w);
            *(uint4*)&Bs[s][NB - 1][bkr][bnq] = u;
        }
    };

    ldg_tile(0);
    sts_tile(0);
    __syncthreads();

    const int nk = KD / BK;
    for (int kt = 0; kt < nk; kt++) {
        const int cur = kt & 1, nxt = cur ^ 1;
        if (kt + 1 < nk) ldg_tile((kt + 1) * BK);

#pragma unroll
        for (int ks = 0; ks < 2; ks++) {
            const int k8 = ks * 8;
            uint32_t af[4][4];
#pragma unroll
            for (int mi = 0; mi < 4; mi++) {
                uint32_t sa = lane_a + (uint32_t)cur * ABUF
                            + (uint32_t)(mi * 16 * (BK + 4) + k8) * 4u;
                ldsm4(af[mi], sa);
            }
            uint32_t bf1[2][2], bf3[2][2];
            const int lg = lane >> 2;
#pragma unroll
            for (int ni = 0; ni < 2; ni++) {
                int c = wn + ni * 8 + lg;
                bf1[ni][0] = Bs[cur][0][k8 + lq][c];
                bf1[ni][1] = Bs[cur][0][k8 + lq + 4][c];
                if (DUAL) {
                    bf3[ni][0] = Bs[cur][NB - 1][k8 + lq][c];
                    bf3[ni][1] = Bs[cur][NB - 1][k8 + lq + 4][c];
                }
            }
#pragma unroll
            for (int mi = 0; mi < 4; mi++)
#pragma unroll
                for (int ni = 0; ni < 2; ni++) {
                    mma8(acc1[mi][ni], af[mi], bf1[ni]);
                    if (DUAL) mma8(acc3[mi][ni], af[mi], bf3[ni]);
                }
        }

        if (kt + 1 < nk) sts_tile(nxt);
        __syncthreads();
    }

    // -------- epilogue --------
    const int lg = lane >> 2;
#pragma unroll
    for (int mi = 0; mi < 4; mi++) {
#pragma unroll
        for (int half = 0; half < 2; half++) {
            int row = m0 + wm + mi * 16 + lg + half * 8;
            if (row >= nrows) continue;
            float* obase;
            if      (MODE == 0) obase = g_H + ((size_t)e * CAP + row) * FF;
            else if (MODE == 1) obase = g_H + ((size_t)(EE * CAP) + row) * FF;
            else if (MODE == 2) obase = g_moe_y + (size_t)g_toklist[e * CAP + row] * DD;
            else                obase = g_mlp_y + (size_t)row * DD;
#pragma unroll
            for (int ni = 0; ni < 2; ni++) {
                int c = n0 + wn + ni * 8 + 2 * lq;
                float2 v;
                if (DUAL) {
                    float h1a = acc1[mi][ni][2 * half + 0];
                    float h1b = acc1[mi][ni][2 * half + 1];
                    float h3a = acc3[mi][ni][2 * half + 0];
                    float h3b = acc3[mi][ni][2 * half + 1];
                    v.x = silu_f(h1a) * h3a;
                    v.y = silu_f(h1b) * h3b;
                } else {
                    v.x = acc1[mi][ni][2 * half + 0];
                    v.y = acc1[mi][ni][2 * half + 1];
                }
                *(float2*)(obase + c) = v;
            }
        }
    }
}

// -------------------- combine: out = coef0*gate*moe + coef1*mlp -----------
__global__ void combine_kernel(float* __restrict__ out)
{
    int i4 = blockIdx.x * blockDim.x + threadIdx.x;
    if (i4 >= T * DD / 4) return;
    int t = i4 >> 8;
    float c1 = g_coef[2 * t + 1];
    float gm = g_kept[t] ? g_coef[2 * t] * g_gateval[t] : 0.f;

    float4 mo = reinterpret_cast<const float4*>(g_moe_y)[i4];
    float4 pl = reinterpret_cast<const float4*>(g_mlp_y)[i4];
    float4 r;
    r.x = gm * mo.x + c1 * pl.x;
    r.y = gm * mo.y + c1 * pl.y;
    r.z = gm * mo.z + c1 * pl.z;
    r.w = gm * mo.w + c1 * pl.w;
    reinterpret_cast<float4*>(out)[i4] = r;
}

// -------------------- launch ----------------------------------------------
extern "C" void kernel_launch(void* const* d_in, const int* in_sizes, int n_in,
                              void* d_out, int out_size)
{
    const float* x   = (const float*)d_in[0];
    const float* wg  = (const float*)d_in[1];
    const float* w1  = (const float*)d_in[2];
    const float* w3  = (const float*)d_in[3];
    const float* w2  = (const float*)d_in[4];
    const float* rw1 = (const float*)d_in[5];
    const float* rw3 = (const float*)d_in[6];
    const float* rw2 = (const float*)d_in[7];
    const float* cw  = (const float*)d_in[8];
    const float* cb  = (const float*)d_in[9];
    float* out = (float*)d_out;

    gating_kernel<<<T, 128>>>(x, wg, cw, cb);
    scan_kernel<<<1, 256>>>(out, out_size);

    // up projections (fused SwiGLU, dual-B tensor GEMM)
    gemm_kernel<0><<<dim3(FF / BN, CAP / BM, EE), 256>>>(x, w1, w3);
    gemm_kernel<1><<<dim3(FF / BN, T   / BM, 1 ), 256>>>(x, rw1, rw3);

    // down projections
    gemm_kernel<2><<<dim3(DD / BN, CAP / BM, EE), 256>>>(nullptr, w2, nullptr);
    gemm_kernel<3><<<dim3(DD / BN, T   / BM, 1 ), 256>>>(nullptr, rw2, nullptr);

    combine_kernel<<<(T * DD / 4 + 255) / 256, 256>>>(out);
}